// round 13
// baseline (speedup 1.0000x reference)
#include <cuda_runtime.h>
#include <cuda_fp16.h>
#include <cstdint>

#define MDIM 8192
#define NDIM 4096
#define KDIM 4096
#define BM 128
#define BN 256
#define BK 64
#define STAGES 4
#define KITERS (KDIM / BK)              /* 64 */
#define A_BYTES (BM * BK * 2)           /* 16384 */
#define B_BYTES (BN * BK * 2)           /* 32768 */
#define STAGE_BYTES (A_BYTES + B_BYTES) /* 49152 */
#define SMEM_TOTAL (STAGES * STAGE_BYTES) /* 196608 */

#define DQ_BLOCKS (NDIM * 128 * 4 / 256)   /* 8192  */
#define XP_BLOCKS (MDIM * 128 * 4 / 256)   /* 16384 */

// Scratch: fp16(rn)-rounded, k-permuted operands (same permutation on A and B).
__device__ __half g_wt[(size_t)NDIM * KDIM];  // W^T: [n][k]
__device__ __half g_xp[(size_t)MDIM * KDIM];  // x:   [m][k]

// ---------------- helpers ----------------
__device__ __forceinline__ uint32_t smem_u32(const void* p) {
    uint32_t a;
    asm("{ .reg .u64 t; cvta.to.shared.u64 t, %1; cvt.u32.u64 %0, t; }" : "=r"(a) : "l"(p));
    return a;
}
__device__ __forceinline__ uint4 lds128(uint32_t a) {
    uint4 v;
    asm volatile("ld.shared.v4.b32 {%0,%1,%2,%3}, [%4];"
                 : "=r"(v.x), "=r"(v.y), "=r"(v.z), "=r"(v.w) : "r"(a));
    return v;
}
__device__ __forceinline__ void cp16(uint32_t dst, const void* src) {
    asm volatile("cp.async.cg.shared.global [%0], [%1], 16;" :: "r"(dst), "l"(src) : "memory");
}
__device__ __forceinline__ void mma16816(float* d, uint32_t a0, uint32_t a1, uint32_t a2,
                                         uint32_t a3, uint32_t b0, uint32_t b1) {
    asm volatile(
        "mma.sync.aligned.m16n8k16.row.col.f32.f16.f16.f32 "
        "{%0,%1,%2,%3}, {%4,%5,%6,%7}, {%8,%9}, {%0,%1,%2,%3};"
        : "+f"(d[0]), "+f"(d[1]), "+f"(d[2]), "+f"(d[3])
        : "r"(a0), "r"(a1), "r"(a2), "r"(a3), "r"(b0), "r"(b1));
}

// ------- kernel 1: merged prep (dequant W + convert x), concurrent blocks -------
__global__ void __launch_bounds__(256) prep_kernel(const int* __restrict__ qw,
                                                   const int* __restrict__ qz,
                                                   const float* __restrict__ sc,
                                                   const float* __restrict__ x) {
    if (blockIdx.x < DQ_BLOCKS) {
        int tid = blockIdx.x * 256 + threadIdx.x;
        int n = tid & (NDIM - 1);
        int rest = tid >> 12;
        int c0 = rest & 3;
        int blk = rest >> 2;
        int grp = blk >> 2;
        int zp = qz[grp * (NDIM / 8) + (n >> 3)];
        int z = ((zp >> ((n & 7) * 4)) & 15) + 1;
        float s = sc[grp * NDIM + n];
        __half2 o[4];
#pragma unroll
        for (int g = 0; g < 4; ++g) {
            int q = qw[(size_t)(blk * 4 + g) * NDIM + n];
            int w0 = (q >> (8 * c0)) & 15;
            int w1 = (q >> (8 * c0 + 4)) & 15;
            o[2 * (g >> 1) + (g & 1)] =
                __floats2half2_rn(s * (float)(w0 - z), s * (float)(w1 - z));
        }
        uint4* dst = (uint4*)((char*)g_wt + (size_t)n * (KDIM * 2) + blk * 64 + c0 * 16);
        *dst = *(uint4*)&o[0];
    } else {
        int tid = (blockIdx.x - DQ_BLOCKS) * 256 + threadIdx.x;
        int c0 = tid & 3;
        int blk = (tid >> 2) & 127;
        int m = tid >> 9;
        const float2* src = (const float2*)(x + (size_t)m * KDIM + blk * 32 + 2 * c0);
        __half2 o[4];
#pragma unroll
        for (int u = 0; u < 4; ++u) {
            float2 f = src[4 * u];
            o[u] = __floats2half2_rn(f.x, f.y);
        }
        uint4* dst = (uint4*)((char*)g_xp + (size_t)m * (KDIM * 2) + blk * 64 + c0 * 16);
        *dst = *(uint4*)&o[0];
    }
}

// ---- kernel 2: fp16 mma.sync GEMM, software-pipelined fragment loads ----
__global__ void __launch_bounds__(256, 1)
gemm_kernel(const float* __restrict__ bias, float* __restrict__ out) {
    extern __shared__ char smem_raw[];
    uint32_t sbase = smem_u32(smem_raw);
    int tid = threadIdx.x;
    int l = tid & 31;
    int wid = tid >> 5;
    int wm = wid & 1;       // 2 m-warps (64 rows each)
    int wn = wid >> 1;      // 4 n-warps (64 cols each)

    // supertile: 8 m-tiles x 16 n-tiles (full N) -> W (32MB fp16) L2-resident
    int bid = blockIdx.x;
    int sup = bid >> 7;
    int loc = bid & 127;
    int m0 = (sup * 8 + (loc & 7)) * BM;
    int n0 = (loc >> 3) * BN;

    // --- async-copy geometry ---
    int cr = tid >> 3;
    int cq = tid & 7;
    const char* a_src = (const char*)g_xp + (size_t)(m0 + cr) * (KDIM * 2) + cq * 16;
    const char* b_src = (const char*)g_wt + (size_t)(n0 + cr) * (KDIM * 2) + cq * 16;
    uint32_t a_dst[4], b_dst[8];
#pragma unroll
    for (int i = 0; i < 4; ++i) {
        int r = cr + 32 * i;
        a_dst[i] = (uint32_t)r * 128u + (uint32_t)(cq ^ (r & 7)) * 16u;
    }
#pragma unroll
    for (int i = 0; i < 8; ++i) {
        int r = cr + 32 * i;
        b_dst[i] = (uint32_t)r * 128u + (uint32_t)(cq ^ (r & 7)) * 16u;
    }

    auto fetch = [&](int it) {
        int s = it & (STAGES - 1);
        uint32_t sa = sbase + s * STAGE_BYTES;
        uint32_t sb = sa + A_BYTES;
        const char* ga = a_src + (size_t)it * (BK * 2);
        const char* gb = b_src + (size_t)it * (BK * 2);
#pragma unroll
        for (int i = 0; i < 4; ++i) cp16(sa + a_dst[i], ga + (size_t)i * 32 * (KDIM * 2));
#pragma unroll
        for (int i = 0; i < 8; ++i) cp16(sb + b_dst[i], gb + (size_t)i * 32 * (KDIM * 2));
    };

#pragma unroll
    for (int i = 0; i < STAGES - 1; ++i) {
        fetch(i);
        asm volatile("cp.async.commit_group;" ::: "memory");
    }

    // --- fragment lds addresses (32k-chunk 0; chunk 1 = ^64; row+8 = +1024) ---
    uint32_t a_off[4];
#pragma unroll
    for (int ms = 0; ms < 4; ++ms) {
        int r = wm * 64 + ms * 16 + (l >> 2);
        a_off[ms] = (uint32_t)r * 128u + (uint32_t)((l & 3) ^ (r & 7)) * 16u;
    }
    uint32_t b_off[8];
#pragma unroll
    for (int ns = 0; ns < 8; ++ns) {
        int r = wn * 64 + ns * 8 + (l >> 2);
        b_off[ns] = (uint32_t)r * 128u + (uint32_t)((l & 3) ^ (r & 7)) * 16u;
    }

    float acc[4][8][4];
#pragma unroll
    for (int ms = 0; ms < 4; ++ms)
#pragma unroll
        for (int ns = 0; ns < 8; ++ns)
#pragma unroll
            for (int i = 0; i < 4; ++i) acc[ms][ns][i] = 0.f;

    for (int it = 0; it < KITERS; ++it) {
        asm volatile("cp.async.wait_group %0;" :: "n"(STAGES - 2) : "memory");
        __syncthreads();
        if (it + STAGES - 1 < KITERS) fetch(it + STAGES - 1);
        asm volatile("cp.async.commit_group;" ::: "memory");

        uint32_t sa = sbase + (it & (STAGES - 1)) * STAGE_BYTES;
        uint32_t sb = sa + A_BYTES;

        // A fragments: double-buffered across the two kc blocks
        uint4 a0r[4], a08[4], a1r[4], a18[4];
#pragma unroll
        for (int ms = 0; ms < 4; ++ms) {
            uint32_t a = sa + a_off[ms];
            a0r[ms] = lds128(a);
            a08[ms] = lds128(a + 1024);
        }

        uint4 bf[2];
#pragma unroll
        for (int kc = 0; kc < 2; ++kc) {
            bf[0] = lds128(sb + (b_off[0] ^ (kc * 64)));
#pragma unroll
            for (int ns = 0; ns < 8; ++ns) {
                // stream next B fragment under this group's MMAs
                if (ns < 7) bf[(ns + 1) & 1] = lds128(sb + (b_off[ns + 1] ^ (kc * 64)));
                // prefetch kc1 A fragments under kc0's last MMA groups
                if (kc == 0 && ns == 6) {
#pragma unroll
                    for (int ms = 0; ms < 4; ++ms)
                        a1r[ms] = lds128(sa + (a_off[ms] ^ 64));
                }
                if (kc == 0 && ns == 7) {
#pragma unroll
                    for (int ms = 0; ms < 4; ++ms)
                        a18[ms] = lds128(sa + (a_off[ms] ^ 64) + 1024);
                }
                const uint4* AR = (kc == 0) ? a0r : a1r;
                const uint4* A8 = (kc == 0) ? a08 : a18;
                uint4 b = bf[ns & 1];
                // k-step 0 across 4 m-frags, then k-step 1 (RAW distance 4)
#pragma unroll
                for (int ms = 0; ms < 4; ++ms)
                    mma16816(acc[ms][ns], AR[ms].x, A8[ms].x, AR[ms].y, A8[ms].y,
                             b.x, b.y);
#pragma unroll
                for (int ms = 0; ms < 4; ++ms)
                    mma16816(acc[ms][ns], AR[ms].z, A8[ms].z, AR[ms].w, A8[ms].w,
                             b.z, b.w);
            }
        }
    }

    // --- epilogue: acc + bias -> out ---
#pragma unroll
    for (int ms = 0; ms < 4; ++ms) {
        int row = m0 + wm * 64 + ms * 16 + (l >> 2);
#pragma unroll
        for (int ns = 0; ns < 8; ++ns) {
            int col = n0 + wn * 64 + ns * 8 + 2 * (l & 3);
            float2 b2 = *(const float2*)(bias + col);
            float2 v0 = make_float2(acc[ms][ns][0] + b2.x, acc[ms][ns][1] + b2.y);
            float2 v1 = make_float2(acc[ms][ns][2] + b2.x, acc[ms][ns][3] + b2.y);
            *(float2*)(out + (size_t)row * NDIM + col) = v0;
            *(float2*)(out + (size_t)(row + 8) * NDIM + col) = v1;
        }
    }
}

// ---------------- launch ----------------
extern "C" void kernel_launch(void* const* d_in, const int* in_sizes, int n_in,
                              void* d_out, int out_size) {
    const float* x    = (const float*)d_in[0];
    const int*   qw   = (const int*)d_in[1];
    const int*   qz   = (const int*)d_in[2];
    const float* sc   = (const float*)d_in[3];
    const float* bias = (const float*)d_in[4];
    float* out = (float*)d_out;

    prep_kernel<<<DQ_BLOCKS + XP_BLOCKS, 256>>>(qw, qz, sc, x);

    cudaFuncSetAttribute(gemm_kernel, cudaFuncAttributeMaxDynamicSharedMemorySize, SMEM_TOTAL);
    gemm_kernel<<<(MDIM / BM) * (NDIM / BN), 256, SMEM_TOTAL>>>(bias, out);
}

// round 14
// speedup vs baseline: 1.3570x; 1.3570x over previous
#include <cuda_runtime.h>
#include <cuda_fp16.h>
#include <cstdint>

#define MDIM 8192
#define NDIM 4096
#define KDIM 4096
#define BM 128
#define BN 256
#define BK 64
#define STAGES 4
#define KITERS (KDIM / BK)              /* 64 */
#define A_BYTES (BM * BK * 2)           /* 16384 */
#define B_BYTES (BN * BK * 2)           /* 32768 */
#define STAGE_BYTES (A_BYTES + B_BYTES) /* 49152 */
#define SMEM_TOTAL (STAGES * STAGE_BYTES) /* 196608 */

#define DQ_BLOCKS 8192    /* 2M threads: one B-quad each */
#define XP_BLOCKS 16384   /* 4M threads: one A-quad each */

// Fragment-major scratch layouts (one 16B quad per mma operand per lane):
// g_wt2: [nblk(16)][it(64)][kc32(2)][nf(32)][l(32)] x 16B  (32 MB)
//        quad = {B[n][k+2b..+1], B[n][k+2b+8..], B[n][k+2b+16..], B[n][k+2b+24..]}
//        n = nblk*256+nf*8+(l>>2), b = l&3, k = it*64+kc32*32
// g_xp2: [mblk(64)][it(64)][kc16(4)][f(8)][l(32)] x 16B    (64 MB)
//        quad = {x[r][k+2b..+1], x[r+8][k..], x[r][k+8+2b..], x[r+8][k+8..]}
//        r = mblk*128+f*16+(l>>2), k = it*64+kc16*16
__device__ __half g_wt2[(size_t)NDIM * KDIM];
__device__ __half g_xp2[(size_t)MDIM * KDIM];

// ---------------- helpers ----------------
__device__ __forceinline__ uint32_t smem_u32(const void* p) {
    uint32_t a;
    asm("{ .reg .u64 t; cvta.to.shared.u64 t, %1; cvt.u32.u64 %0, t; }" : "=r"(a) : "l"(p));
    return a;
}
__device__ __forceinline__ uint4 lds128(uint32_t a) {
    uint4 v;
    asm volatile("ld.shared.v4.b32 {%0,%1,%2,%3}, [%4];"
                 : "=r"(v.x), "=r"(v.y), "=r"(v.z), "=r"(v.w) : "r"(a));
    return v;
}
__device__ __forceinline__ void cp16(uint32_t dst, const void* src) {
    asm volatile("cp.async.cg.shared.global [%0], [%1], 16;" :: "r"(dst), "l"(src) : "memory");
}
__device__ __forceinline__ void mma16816(float* d, uint32_t a0, uint32_t a1, uint32_t a2,
                                         uint32_t a3, uint32_t b0, uint32_t b1) {
    asm volatile(
        "mma.sync.aligned.m16n8k16.row.col.f32.f16.f16.f32 "
        "{%0,%1,%2,%3}, {%4,%5,%6,%7}, {%8,%9}, {%0,%1,%2,%3};"
        : "+f"(d[0]), "+f"(d[1]), "+f"(d[2]), "+f"(d[3])
        : "r"(a0), "r"(a1), "r"(a2), "r"(a3), "r"(b0), "r"(b1));
}

// ------- kernel 1: merged prep, fragment-major outputs, coalesced writes -------
__global__ void __launch_bounds__(256) prep_kernel(const int* __restrict__ qw,
                                                   const int* __restrict__ qz,
                                                   const float* __restrict__ sc,
                                                   const float* __restrict__ x) {
    if (blockIdx.x < DQ_BLOCKS) {
        // --- GPTQ dequant -> fp16 B quads ---
        int idx = blockIdx.x * 256 + threadIdx.x;   // 2M
        int l = idx & 31;
        int nf = (idx >> 5) & 31;
        int kc32 = (idx >> 10) & 1;
        int it = (idx >> 11) & 63;
        int nblk = idx >> 17;
        int n = nblk * 256 + nf * 8 + (l >> 2);
        int b = l & 3;
        int kbase = it * 64 + kc32 * 32;
        int r0 = kbase >> 3;                        // qweight row (8 k per row)
        int grp = kbase >> 7;                       // 128-k GPTQ group
        int zp = qz[grp * (NDIM / 8) + (n >> 3)];
        int z = ((zp >> ((n & 7) * 4)) & 15) + 1;
        float s = sc[grp * NDIM + n];
        __half2 o[4];
#pragma unroll
        for (int g = 0; g < 4; ++g) {               // k offsets 8g + {2b, 2b+1}
            int q = qw[(size_t)(r0 + g) * NDIM + n];
            int w0 = (q >> (8 * b)) & 15;
            int w1 = (q >> (8 * b + 4)) & 15;
            o[g] = __floats2half2_rn(s * (float)(w0 - z), s * (float)(w1 - z));
        }
        ((uint4*)g_wt2)[idx] = *(uint4*)&o[0];
    } else {
        // --- x -> fp16 A quads ---
        int idx = (blockIdx.x - DQ_BLOCKS) * 256 + threadIdx.x;  // 4M
        int l = idx & 31;
        int f = (idx >> 5) & 7;
        int kc16 = (idx >> 8) & 3;
        int it = (idx >> 10) & 63;
        int mblk = idx >> 16;
        int b = l & 3;
        int r = mblk * 128 + f * 16 + (l >> 2);
        int k0 = it * 64 + kc16 * 16 + 2 * b;
        const float* xr = x + (size_t)r * KDIM;
        float2 lo  = *(const float2*)(xr + k0);
        float2 hi  = *(const float2*)(xr + k0 + 8);
        float2 lo8 = *(const float2*)(xr + 8 * KDIM + k0);
        float2 hi8 = *(const float2*)(xr + 8 * KDIM + k0 + 8);
        __half2 o[4];
        o[0] = __floats2half2_rn(lo.x, lo.y);       // a0: row r,   k lo
        o[1] = __floats2half2_rn(lo8.x, lo8.y);     // a1: row r+8, k lo
        o[2] = __floats2half2_rn(hi.x, hi.y);       // a2: row r,   k hi
        o[3] = __floats2half2_rn(hi8.x, hi8.y);     // a3: row r+8, k hi
        ((uint4*)g_xp2)[idx] = *(uint4*)&o[0];
    }
}

// ---- kernel 2: fp16 mma.sync GEMM, MOV-free fragment-major mainloop ----
__global__ void __launch_bounds__(256, 1)
gemm_kernel(const float* __restrict__ bias, float* __restrict__ out) {
    extern __shared__ char smem_raw[];
    uint32_t sbase = smem_u32(smem_raw);
    int tid = threadIdx.x;
    int l = tid & 31;
    int wid = tid >> 5;
    int wm = wid & 1;       // 2 m-warps (64 rows each)
    int wn = wid >> 1;      // 4 n-warps (64 cols each)

    // supertile: 8 m-tiles x 16 n-tiles (full N) -> W (32MB fp16) L2-resident
    int bid = blockIdx.x;
    int sup = bid >> 7;
    int loc = bid & 127;
    int mblk = sup * 8 + (loc & 7);     // 0..63
    int nblk = loc >> 3;                // 0..15
    int m0 = mblk * BM;
    int n0 = nblk * BN;

    const char* a_gbase = (const char*)g_xp2 + (size_t)mblk * 64 * A_BYTES;
    const char* b_gbase = (const char*)g_wt2 + (size_t)nblk * 64 * B_BYTES;

    auto fetch = [&](int it) {
        int s = it & (STAGES - 1);
        uint32_t sa = sbase + s * STAGE_BYTES;
        uint32_t sb = sa + A_BYTES;
        const char* ga = a_gbase + (size_t)it * A_BYTES;
        const char* gb = b_gbase + (size_t)it * B_BYTES;
#pragma unroll
        for (int i = 0; i < 4; ++i)
            cp16(sa + tid * 16 + i * 4096, ga + tid * 16 + i * 4096);
#pragma unroll
        for (int i = 0; i < 8; ++i)
            cp16(sb + tid * 16 + i * 4096, gb + tid * 16 + i * 4096);
    };

#pragma unroll
    for (int i = 0; i < STAGES - 1; ++i) {
        fetch(i);
        asm volatile("cp.async.commit_group;" ::: "memory");
    }

    uint32_t aoff = (uint32_t)(wm * 4 * 512 + l * 16);   // + kc16*4096 + ms*512
    uint32_t boff = (uint32_t)(wn * 8 * 512 + l * 16);   // + kc32*16384 + ns*512

    float acc[4][8][4];
#pragma unroll
    for (int ms = 0; ms < 4; ++ms)
#pragma unroll
        for (int ns = 0; ns < 8; ++ns)
#pragma unroll
            for (int i = 0; i < 4; ++i) acc[ms][ns][i] = 0.f;

    for (int it = 0; it < KITERS; ++it) {
        asm volatile("cp.async.wait_group %0;" :: "n"(STAGES - 2) : "memory");
        __syncthreads();
        if (it + STAGES - 1 < KITERS) fetch(it + STAGES - 1);
        asm volatile("cp.async.commit_group;" ::: "memory");

        uint32_t sa = sbase + (it & (STAGES - 1)) * STAGE_BYTES;
        uint32_t sb = sa + A_BYTES;
#pragma unroll
        for (int kc32 = 0; kc32 < 2; ++kc32) {
            uint4 bf[8];
#pragma unroll
            for (int ns = 0; ns < 8; ++ns)
                bf[ns] = lds128(sb + kc32 * 16384 + boff + ns * 512);
#pragma unroll
            for (int h = 0; h < 2; ++h) {           // two k16 steps per kc32
                uint4 aq[4];
#pragma unroll
                for (int ms = 0; ms < 4; ++ms)
                    aq[ms] = lds128(sa + (kc32 * 2 + h) * 4096 + aoff + ms * 512);
#pragma unroll
                for (int ms = 0; ms < 4; ++ms) {
#pragma unroll
                    for (int ns = 0; ns < 8; ++ns) {
                        if (h == 0)
                            mma16816(acc[ms][ns], aq[ms].x, aq[ms].y, aq[ms].z,
                                     aq[ms].w, bf[ns].x, bf[ns].y);
                        else
                            mma16816(acc[ms][ns], aq[ms].x, aq[ms].y, aq[ms].z,
                                     aq[ms].w, bf[ns].z, bf[ns].w);
                    }
                }
            }
        }
    }

    // --- epilogue: acc + bias -> out ---
#pragma unroll
    for (int ms = 0; ms < 4; ++ms) {
        int row = m0 + wm * 64 + ms * 16 + (l >> 2);
#pragma unroll
        for (int ns = 0; ns < 8; ++ns) {
            int col = n0 + wn * 64 + ns * 8 + 2 * (l & 3);
            float2 b2 = *(const float2*)(bias + col);
            float2 v0 = make_float2(acc[ms][ns][0] + b2.x, acc[ms][ns][1] + b2.y);
            float2 v1 = make_float2(acc[ms][ns][2] + b2.x, acc[ms][ns][3] + b2.y);
            *(float2*)(out + (size_t)row * NDIM + col) = v0;
            *(float2*)(out + (size_t)(row + 8) * NDIM + col) = v1;
        }
    }
}

// ---------------- launch ----------------
extern "C" void kernel_launch(void* const* d_in, const int* in_sizes, int n_in,
                              void* d_out, int out_size) {
    const float* x    = (const float*)d_in[0];
    const int*   qw   = (const int*)d_in[1];
    const int*   qz   = (const int*)d_in[2];
    const float* sc   = (const float*)d_in[3];
    const float* bias = (const float*)d_in[4];
    float* out = (float*)d_out;

    prep_kernel<<<DQ_BLOCKS + XP_BLOCKS, 256>>>(qw, qz, sc, x);

    cudaFuncSetAttribute(gemm_kernel, cudaFuncAttributeMaxDynamicSharedMemorySize, SMEM_TOTAL);
    gemm_kernel<<<(MDIM / BM) * (NDIM / BN), 256, SMEM_TOTAL>>>(bias, out);
}

// round 15
// speedup vs baseline: 1.4141x; 1.0421x over previous
#include <cuda_runtime.h>
#include <cuda_fp16.h>
#include <cstdint>

#define MDIM 8192
#define NDIM 4096
#define KDIM 4096
#define BM 128
#define BN 256
#define BK 64
#define STAGES 4
#define KITERS (KDIM / BK)              /* 64 */
#define A_BYTES (BM * BK * 2)           /* 16384 */
#define B_BYTES (BN * BK * 2)           /* 32768 */
#define STAGE_BYTES (A_BYTES + B_BYTES) /* 49152 */
#define SMEM_TOTAL (STAGES * STAGE_BYTES) /* 196608 */

#define DQ_BLOCKS 8192    /* 2M threads: one B-quad each */
#define XP_BLOCKS 16384   /* 4M threads: one A-quad each */

// Fragment-major scratch (one 16B quad per lds128, MMA-ready):
// g_wt2: [nblk(16)][it(64)][kc16(4)][nf(16)][l(32)] x 16B   (32 MB)
//   quad = {b0(n), b1(n), b0(n+8), b1(n+8)} for k16 step kc16
//   n = nblk*256 + nf*16 + (l>>2); b0 = k0+2b,2b+1; b1 = k0+8+2b,..; b = l&3
// g_xp2: [mblk(64)][it(64)][kc16(4)][f(8)][l(32)] x 16B     (64 MB)
//   quad = {a0,a1,a2,a3}: rows r/r+8, k lo/hi pairs; r = mblk*128+f*16+(l>>2)
__device__ __half g_wt2[(size_t)NDIM * KDIM];
__device__ __half g_xp2[(size_t)MDIM * KDIM];

// ---------------- helpers ----------------
__device__ __forceinline__ uint32_t smem_u32(const void* p) {
    uint32_t a;
    asm("{ .reg .u64 t; cvta.to.shared.u64 t, %1; cvt.u32.u64 %0, t; }" : "=r"(a) : "l"(p));
    return a;
}
__device__ __forceinline__ uint4 lds128(uint32_t a) {
    uint4 v;
    asm volatile("ld.shared.v4.b32 {%0,%1,%2,%3}, [%4];"
                 : "=r"(v.x), "=r"(v.y), "=r"(v.z), "=r"(v.w) : "r"(a));
    return v;
}
__device__ __forceinline__ void cp16(uint32_t dst, const void* src) {
    asm volatile("cp.async.cg.shared.global [%0], [%1], 16;" :: "r"(dst), "l"(src) : "memory");
}
__device__ __forceinline__ void mma16816(float* d, uint32_t a0, uint32_t a1, uint32_t a2,
                                         uint32_t a3, uint32_t b0, uint32_t b1) {
    asm volatile(
        "mma.sync.aligned.m16n8k16.row.col.f32.f16.f16.f32 "
        "{%0,%1,%2,%3}, {%4,%5,%6,%7}, {%8,%9}, {%0,%1,%2,%3};"
        : "+f"(d[0]), "+f"(d[1]), "+f"(d[2]), "+f"(d[3])
        : "r"(a0), "r"(a1), "r"(a2), "r"(a3), "r"(b0), "r"(b1));
}

// ------- kernel 1: merged prep, fragment-major outputs -------
__global__ void __launch_bounds__(256) prep_kernel(const int* __restrict__ qw,
                                                   const int* __restrict__ qz,
                                                   const float* __restrict__ sc,
                                                   const float* __restrict__ x) {
    if (blockIdx.x < DQ_BLOCKS) {
        // --- GPTQ dequant -> fp16 B pair-quads ---
        int idx = blockIdx.x * 256 + threadIdx.x;   // 2M
        int l = idx & 31;
        int nf = (idx >> 5) & 15;
        int kc16 = (idx >> 9) & 3;
        int it = (idx >> 11) & 63;
        int nblk = idx >> 17;
        int b = l & 3;
        int n = nblk * 256 + nf * 16 + (l >> 2);
        int n8 = n + 8;
        int k0 = it * 64 + kc16 * 16;
        int r0 = k0 >> 3;                           // qweight row (8 k per word)
        int grp = k0 >> 7;                          // 128-k GPTQ group
        int zp  = qz[grp * (NDIM / 8) + (n >> 3)];
        int zp8 = qz[grp * (NDIM / 8) + (n8 >> 3)];
        int z  = ((zp  >> ((n  & 7) * 4)) & 15) + 1;
        int z8 = ((zp8 >> ((n8 & 7) * 4)) & 15) + 1;
        float s  = sc[grp * NDIM + n];
        float s8 = sc[grp * NDIM + n8];
        int q00 = qw[(size_t)r0 * NDIM + n];
        int q10 = qw[(size_t)(r0 + 1) * NDIM + n];
        int q08 = qw[(size_t)r0 * NDIM + n8];
        int q18 = qw[(size_t)(r0 + 1) * NDIM + n8];
        __half2 o[4];
        o[0] = __floats2half2_rn(s  * (float)(((q00 >> (8 * b)) & 15) - z),
                                 s  * (float)(((q00 >> (8 * b + 4)) & 15) - z));
        o[1] = __floats2half2_rn(s  * (float)(((q10 >> (8 * b)) & 15) - z),
                                 s  * (float)(((q10 >> (8 * b + 4)) & 15) - z));
        o[2] = __floats2half2_rn(s8 * (float)(((q08 >> (8 * b)) & 15) - z8),
                                 s8 * (float)(((q08 >> (8 * b + 4)) & 15) - z8));
        o[3] = __floats2half2_rn(s8 * (float)(((q18 >> (8 * b)) & 15) - z8),
                                 s8 * (float)(((q18 >> (8 * b + 4)) & 15) - z8));
        ((uint4*)g_wt2)[idx] = *(uint4*)&o[0];
    } else {
        // --- x -> fp16 A quads (unchanged from R14) ---
        int idx = (blockIdx.x - DQ_BLOCKS) * 256 + threadIdx.x;  // 4M
        int l = idx & 31;
        int f = (idx >> 5) & 7;
        int kc16 = (idx >> 8) & 3;
        int it = (idx >> 10) & 63;
        int mblk = idx >> 16;
        int b = l & 3;
        int r = mblk * 128 + f * 16 + (l >> 2);
        int k0 = it * 64 + kc16 * 16 + 2 * b;
        const float* xr = x + (size_t)r * KDIM;
        float2 lo  = *(const float2*)(xr + k0);
        float2 hi  = *(const float2*)(xr + k0 + 8);
        float2 lo8 = *(const float2*)(xr + 8 * KDIM + k0);
        float2 hi8 = *(const float2*)(xr + 8 * KDIM + k0 + 8);
        __half2 o[4];
        o[0] = __floats2half2_rn(lo.x, lo.y);
        o[1] = __floats2half2_rn(lo8.x, lo8.y);
        o[2] = __floats2half2_rn(hi.x, hi.y);
        o[3] = __floats2half2_rn(hi8.x, hi8.y);
        ((uint4*)g_xp2)[idx] = *(uint4*)&o[0];
    }
}

// ---- kernel 2: fp16 mma.sync GEMM, uniform k16 groups, double-buffered ----
__global__ void __launch_bounds__(256, 1)
gemm_kernel(const float* __restrict__ bias, float* __restrict__ out) {
    extern __shared__ char smem_raw[];
    uint32_t sbase = smem_u32(smem_raw);
    int tid = threadIdx.x;
    int l = tid & 31;
    int wid = tid >> 5;
    int wm = wid & 1;       // 2 m-warps (64 rows each)
    int wn = wid >> 1;      // 4 n-warps (64 cols each)

    // supertile: 8 m-tiles x 16 n-tiles (full N) -> W (32MB fp16) L2-resident
    int bid = blockIdx.x;
    int sup = bid >> 7;
    int loc = bid & 127;
    int mblk = sup * 8 + (loc & 7);
    int nblk = loc >> 3;
    int m0 = mblk * BM;
    int n0 = nblk * BN;

    const char* a_gbase = (const char*)g_xp2 + (size_t)mblk * 64 * A_BYTES;
    const char* b_gbase = (const char*)g_wt2 + (size_t)nblk * 64 * B_BYTES;

    auto fetch = [&](int it) {
        int s = it & (STAGES - 1);
        uint32_t sa = sbase + s * STAGE_BYTES;
        uint32_t sb = sa + A_BYTES;
        const char* ga = a_gbase + (size_t)it * A_BYTES;
        const char* gb = b_gbase + (size_t)it * B_BYTES;
#pragma unroll
        for (int i = 0; i < 4; ++i)
            cp16(sa + tid * 16 + i * 4096, ga + tid * 16 + i * 4096);
#pragma unroll
        for (int i = 0; i < 8; ++i)
            cp16(sb + tid * 16 + i * 4096, gb + tid * 16 + i * 4096);
    };

#pragma unroll
    for (int i = 0; i < STAGES - 1; ++i) {
        fetch(i);
        asm volatile("cp.async.commit_group;" ::: "memory");
    }

    uint32_t aoff = (uint32_t)(wm * 2048 + l * 16);   // + kc16*4096 + ms*512
    uint32_t boff = (uint32_t)(wn * 2048 + l * 16);   // + kc16*8192 + p*512

    float acc[4][8][4];
#pragma unroll
    for (int ms = 0; ms < 4; ++ms)
#pragma unroll
        for (int ns = 0; ns < 8; ++ns)
#pragma unroll
            for (int i = 0; i < 4; ++i) acc[ms][ns][i] = 0.f;

    for (int it = 0; it < KITERS; ++it) {
        asm volatile("cp.async.wait_group %0;" :: "n"(STAGES - 2) : "memory");
        __syncthreads();
        if (it + STAGES - 1 < KITERS) fetch(it + STAGES - 1);
        asm volatile("cp.async.commit_group;" ::: "memory");

        uint32_t sa = sbase + (it & (STAGES - 1)) * STAGE_BYTES;
        uint32_t sb = sa + A_BYTES;

        uint4 aq[2][4], bq[2][4];
        // load group 0
#pragma unroll
        for (int ms = 0; ms < 4; ++ms) aq[0][ms] = lds128(sa + aoff + ms * 512);
#pragma unroll
        for (int p = 0; p < 4; ++p) bq[0][p] = lds128(sb + boff + p * 512);

#pragma unroll
        for (int g = 0; g < 4; ++g) {           // 4 uniform k16 groups
            int cur = g & 1, nxt = cur ^ 1;
            if (g < 3) {                        // prefetch group g+1 under g's MMAs
#pragma unroll
                for (int ms = 0; ms < 4; ++ms)
                    aq[nxt][ms] = lds128(sa + (g + 1) * 4096 + aoff + ms * 512);
#pragma unroll
                for (int p = 0; p < 4; ++p)
                    bq[nxt][p] = lds128(sb + (g + 1) * 8192 + boff + p * 512);
            }
#pragma unroll
            for (int ms = 0; ms < 4; ++ms) {
#pragma unroll
                for (int p = 0; p < 4; ++p) {
                    mma16816(acc[ms][2 * p], aq[cur][ms].x, aq[cur][ms].y,
                             aq[cur][ms].z, aq[cur][ms].w, bq[cur][p].x, bq[cur][p].y);
                    mma16816(acc[ms][2 * p + 1], aq[cur][ms].x, aq[cur][ms].y,
                             aq[cur][ms].z, aq[cur][ms].w, bq[cur][p].z, bq[cur][p].w);
                }
            }
        }
    }

    // --- epilogue: acc + bias -> out ---
#pragma unroll
    for (int ms = 0; ms < 4; ++ms) {
        int row = m0 + wm * 64 + ms * 16 + (l >> 2);
#pragma unroll
        for (int ns = 0; ns < 8; ++ns) {
            int col = n0 + wn * 64 + (ns >> 1) * 16 + (ns & 1) * 8 + 2 * (l & 3);
            float2 b2 = *(const float2*)(bias + col);
            float2 v0 = make_float2(acc[ms][ns][0] + b2.x, acc[ms][ns][1] + b2.y);
            float2 v1 = make_float2(acc[ms][ns][2] + b2.x, acc[ms][ns][3] + b2.y);
            *(float2*)(out + (size_t)row * NDIM + col) = v0;
            *(float2*)(out + (size_t)(row + 8) * NDIM + col) = v1;
        }
    }
}

// ---------------- launch ----------------
extern "C" void kernel_launch(void* const* d_in, const int* in_sizes, int n_in,
                              void* d_out, int out_size) {
    const float* x    = (const float*)d_in[0];
    const int*   qw   = (const int*)d_in[1];
    const int*   qz   = (const int*)d_in[2];
    const float* sc   = (const float*)d_in[3];
    const float* bias = (const float*)d_in[4];
    float* out = (float*)d_out;

    prep_kernel<<<DQ_BLOCKS + XP_BLOCKS, 256>>>(qw, qz, sc, x);

    cudaFuncSetAttribute(gemm_kernel, cudaFuncAttributeMaxDynamicSharedMemorySize, SMEM_TOTAL);
    gemm_kernel<<<(MDIM / BM) * (NDIM / BN), 256, SMEM_TOTAL>>>(bias, out);
}

// round 16
// speedup vs baseline: 1.4435x; 1.0207x over previous
#include <cuda_runtime.h>
#include <cuda_fp16.h>
#include <cstdint>

#define MDIM 8192
#define NDIM 4096
#define KDIM 4096
#define BM 128
#define BN 256
#define BK 128                          /* 2 k64-blocks per iter */
#define KITERS (KDIM / BK)              /* 32 */
#define A_STAGE (BM * BK * 2)           /* 32768 */
#define B_STAGE (BN * BK * 2)           /* 65536 */
#define STAGE_BYTES (A_STAGE + B_STAGE) /* 98304 */
#define SMEM_TOTAL (2 * STAGE_BYTES)    /* 196608 */

#define DQ_BLOCKS 8192    /* 2M threads: one B-quad each */
#define XP_BLOCKS 16384   /* 4M threads: one A-quad each */

// Fragment-major scratch (one 16B quad per lds128, MMA-ready):
// g_wt2: [nblk(16)][it64(64)][kc16(4)][nf(16)][l(32)] x 16B   (32 MB)
//   quad = {b0(n), b1(n), b0(n+8), b1(n+8)} for k16 step kc16
// g_xp2: [mblk(64)][it64(64)][kc16(4)][f(8)][l(32)] x 16B     (64 MB)
//   quad = {a0,a1,a2,a3}: rows r/r+8, k lo/hi pairs
// Two consecutive it64 blocks are contiguous -> BK=128 stage is one block copy.
__device__ __half g_wt2[(size_t)NDIM * KDIM];
__device__ __half g_xp2[(size_t)MDIM * KDIM];

// ---------------- helpers ----------------
__device__ __forceinline__ uint32_t smem_u32(const void* p) {
    uint32_t a;
    asm("{ .reg .u64 t; cvta.to.shared.u64 t, %1; cvt.u32.u64 %0, t; }" : "=r"(a) : "l"(p));
    return a;
}
__device__ __forceinline__ uint4 lds128(uint32_t a) {
    uint4 v;
    asm volatile("ld.shared.v4.b32 {%0,%1,%2,%3}, [%4];"
                 : "=r"(v.x), "=r"(v.y), "=r"(v.z), "=r"(v.w) : "r"(a));
    return v;
}
__device__ __forceinline__ void cp16(uint32_t dst, const void* src) {
    asm volatile("cp.async.cg.shared.global [%0], [%1], 16;" :: "r"(dst), "l"(src) : "memory");
}
__device__ __forceinline__ void mma16816(float* d, uint32_t a0, uint32_t a1, uint32_t a2,
                                         uint32_t a3, uint32_t b0, uint32_t b1) {
    asm volatile(
        "mma.sync.aligned.m16n8k16.row.col.f32.f16.f16.f32 "
        "{%0,%1,%2,%3}, {%4,%5,%6,%7}, {%8,%9}, {%0,%1,%2,%3};"
        : "+f"(d[0]), "+f"(d[1]), "+f"(d[2]), "+f"(d[3])
        : "r"(a0), "r"(a1), "r"(a2), "r"(a3), "r"(b0), "r"(b1));
}

// ------- kernel 1: merged prep, fragment-major outputs (unchanged from R15) -------
__global__ void __launch_bounds__(256) prep_kernel(const int* __restrict__ qw,
                                                   const int* __restrict__ qz,
                                                   const float* __restrict__ sc,
                                                   const float* __restrict__ x) {
    if (blockIdx.x < DQ_BLOCKS) {
        int idx = blockIdx.x * 256 + threadIdx.x;   // 2M
        int l = idx & 31;
        int nf = (idx >> 5) & 15;
        int kc16 = (idx >> 9) & 3;
        int it = (idx >> 11) & 63;
        int nblk = idx >> 17;
        int b = l & 3;
        int n = nblk * 256 + nf * 16 + (l >> 2);
        int n8 = n + 8;
        int k0 = it * 64 + kc16 * 16;
        int r0 = k0 >> 3;
        int grp = k0 >> 7;
        int zp  = qz[grp * (NDIM / 8) + (n >> 3)];
        int zp8 = qz[grp * (NDIM / 8) + (n8 >> 3)];
        int z  = ((zp  >> ((n  & 7) * 4)) & 15) + 1;
        int z8 = ((zp8 >> ((n8 & 7) * 4)) & 15) + 1;
        float s  = sc[grp * NDIM + n];
        float s8 = sc[grp * NDIM + n8];
        int q00 = qw[(size_t)r0 * NDIM + n];
        int q10 = qw[(size_t)(r0 + 1) * NDIM + n];
        int q08 = qw[(size_t)r0 * NDIM + n8];
        int q18 = qw[(size_t)(r0 + 1) * NDIM + n8];
        __half2 o[4];
        o[0] = __floats2half2_rn(s  * (float)(((q00 >> (8 * b)) & 15) - z),
                                 s  * (float)(((q00 >> (8 * b + 4)) & 15) - z));
        o[1] = __floats2half2_rn(s  * (float)(((q10 >> (8 * b)) & 15) - z),
                                 s  * (float)(((q10 >> (8 * b + 4)) & 15) - z));
        o[2] = __floats2half2_rn(s8 * (float)(((q08 >> (8 * b)) & 15) - z8),
                                 s8 * (float)(((q08 >> (8 * b + 4)) & 15) - z8));
        o[3] = __floats2half2_rn(s8 * (float)(((q18 >> (8 * b)) & 15) - z8),
                                 s8 * (float)(((q18 >> (8 * b + 4)) & 15) - z8));
        ((uint4*)g_wt2)[idx] = *(uint4*)&o[0];
    } else {
        int idx = (blockIdx.x - DQ_BLOCKS) * 256 + threadIdx.x;  // 4M
        int l = idx & 31;
        int f = (idx >> 5) & 7;
        int kc16 = (idx >> 8) & 3;
        int it = (idx >> 10) & 63;
        int mblk = idx >> 16;
        int b = l & 3;
        int r = mblk * 128 + f * 16 + (l >> 2);
        int k0 = it * 64 + kc16 * 16 + 2 * b;
        const float* xr = x + (size_t)r * KDIM;
        float2 lo  = *(const float2*)(xr + k0);
        float2 hi  = *(const float2*)(xr + k0 + 8);
        float2 lo8 = *(const float2*)(xr + 8 * KDIM + k0);
        float2 hi8 = *(const float2*)(xr + 8 * KDIM + k0 + 8);
        __half2 o[4];
        o[0] = __floats2half2_rn(lo.x, lo.y);
        o[1] = __floats2half2_rn(lo8.x, lo8.y);
        o[2] = __floats2half2_rn(hi.x, hi.y);
        o[3] = __floats2half2_rn(hi8.x, hi8.y);
        ((uint4*)g_xp2)[idx] = *(uint4*)&o[0];
    }
}

// ---- kernel 2: fp16 mma.sync GEMM, BK=128, 2 stages, 8 double-buffered groups ----
__global__ void __launch_bounds__(256, 1)
gemm_kernel(const float* __restrict__ bias, float* __restrict__ out) {
    extern __shared__ char smem_raw[];
    uint32_t sbase = smem_u32(smem_raw);
    int tid = threadIdx.x;
    int l = tid & 31;
    int wid = tid >> 5;
    int wm = wid & 1;       // 2 m-warps (64 rows each)
    int wn = wid >> 1;      // 4 n-warps (64 cols each)

    // supertile: 8 m-tiles x 16 n-tiles (full N) -> W (32MB fp16) L2-resident
    int bid = blockIdx.x;
    int sup = bid >> 7;
    int loc = bid & 127;
    int mblk = sup * 8 + (loc & 7);
    int nblk = loc >> 3;
    int m0 = mblk * BM;
    int n0 = nblk * BN;

    const char* a_gbase = (const char*)g_xp2 + (size_t)mblk * 64 * 16384;
    const char* b_gbase = (const char*)g_wt2 + (size_t)nblk * 64 * 32768;

    auto fetch = [&](int it) {
        int s = it & 1;
        uint32_t sa = sbase + s * STAGE_BYTES;
        uint32_t sb = sa + A_STAGE;
        const char* ga = a_gbase + (size_t)it * A_STAGE;
        const char* gb = b_gbase + (size_t)it * B_STAGE;
#pragma unroll
        for (int i = 0; i < 8; ++i)
            cp16(sa + tid * 16 + i * 4096, ga + tid * 16 + i * 4096);
#pragma unroll
        for (int i = 0; i < 16; ++i)
            cp16(sb + tid * 16 + i * 4096, gb + tid * 16 + i * 4096);
    };

    fetch(0);
    asm volatile("cp.async.commit_group;" ::: "memory");

    uint32_t aoff = (uint32_t)(wm * 2048 + l * 16);   // + g*4096 + ms*512
    uint32_t boff = (uint32_t)(wn * 2048 + l * 16);   // + g*8192 + p*512

    float acc[4][8][4];
#pragma unroll
    for (int ms = 0; ms < 4; ++ms)
#pragma unroll
        for (int ns = 0; ns < 8; ++ns)
#pragma unroll
            for (int i = 0; i < 4; ++i) acc[ms][ns][i] = 0.f;

    for (int it = 0; it < KITERS; ++it) {
        asm volatile("cp.async.wait_group 0;" ::: "memory");
        __syncthreads();
        if (it + 1 < KITERS) fetch(it + 1);
        asm volatile("cp.async.commit_group;" ::: "memory");

        uint32_t sa = sbase + (it & 1) * STAGE_BYTES;
        uint32_t sb = sa + A_STAGE;

        uint4 aq[2][4], bq[2][4];
#pragma unroll
        for (int ms = 0; ms < 4; ++ms) aq[0][ms] = lds128(sa + aoff + ms * 512);
#pragma unroll
        for (int p = 0; p < 4; ++p) bq[0][p] = lds128(sb + boff + p * 512);

#pragma unroll
        for (int g = 0; g < 8; ++g) {           // 8 uniform k16 groups (BK=128)
            int cur = g & 1, nxt = cur ^ 1;
            if (g < 7) {                        // prefetch group g+1 under g's MMAs
#pragma unroll
                for (int ms = 0; ms < 4; ++ms)
                    aq[nxt][ms] = lds128(sa + (g + 1) * 4096 + aoff + ms * 512);
#pragma unroll
                for (int p = 0; p < 4; ++p)
                    bq[nxt][p] = lds128(sb + (g + 1) * 8192 + boff + p * 512);
            }
#pragma unroll
            for (int ms = 0; ms < 4; ++ms) {
#pragma unroll
                for (int p = 0; p < 4; ++p) {
                    mma16816(acc[ms][2 * p], aq[cur][ms].x, aq[cur][ms].y,
                             aq[cur][ms].z, aq[cur][ms].w, bq[cur][p].x, bq[cur][p].y);
                    mma16816(acc[ms][2 * p + 1], aq[cur][ms].x, aq[cur][ms].y,
                             aq[cur][ms].z, aq[cur][ms].w, bq[cur][p].z, bq[cur][p].w);
                }
            }
        }
    }

    // --- epilogue: acc + bias -> out ---
#pragma unroll
    for (int ms = 0; ms < 4; ++ms) {
        int row = m0 + wm * 64 + ms * 16 + (l >> 2);
#pragma unroll
        for (int ns = 0; ns < 8; ++ns) {
            int col = n0 + wn * 64 + (ns >> 1) * 16 + (ns & 1) * 8 + 2 * (l & 3);
            float2 b2 = *(const float2*)(bias + col);
            float2 v0 = make_float2(acc[ms][ns][0] + b2.x, acc[ms][ns][1] + b2.y);
            float2 v1 = make_float2(acc[ms][ns][2] + b2.x, acc[ms][ns][3] + b2.y);
            *(float2*)(out + (size_t)row * NDIM + col) = v0;
            *(float2*)(out + (size_t)(row + 8) * NDIM + col) = v1;
        }
    }
}

// ---------------- launch ----------------
extern "C" void kernel_launch(void* const* d_in, const int* in_sizes, int n_in,
                              void* d_out, int out_size) {
    const float* x    = (const float*)d_in[0];
    const int*   qw   = (const int*)d_in[1];
    const int*   qz   = (const int*)d_in[2];
    const float* sc   = (const float*)d_in[3];
    const float* bias = (const float*)d_in[4];
    float* out = (float*)d_out;

    prep_kernel<<<DQ_BLOCKS + XP_BLOCKS, 256>>>(qw, qz, sc, x);

    cudaFuncSetAttribute(gemm_kernel, cudaFuncAttributeMaxDynamicSharedMemorySize, SMEM_TOTAL);
    gemm_kernel<<<(MDIM / BM) * (NDIM / BN), 256, SMEM_TOTAL>>>(bias, out);
}

// round 17
// speedup vs baseline: 1.5007x; 1.0397x over previous
#include <cuda_runtime.h>
#include <cuda_fp16.h>
#include <cstdint>

#define MDIM 8192
#define NDIM 4096
#define KDIM 4096
#define BM 128
#define BN 256
#define BK 128                          /* 2 k64-blocks per iter */
#define KITERS (KDIM / BK)              /* 32 */
#define A_STAGE (BM * BK * 2)           /* 32768 */
#define B_STAGE (BN * BK * 2)           /* 65536 */
#define STAGE_BYTES (A_STAGE + B_STAGE) /* 98304 */
#define SMEM_TOTAL (2 * STAGE_BYTES)    /* 196608 */

#define DQ_BLOCKS 8192    /* 2M threads: one B-quad each */
#define XP_BLOCKS 16384   /* 4M threads: one A-quad each */

// Fragment-major scratch (one 16B quad per lds128, MMA-ready):
// g_wt2: [nblk(16)][it64(64)][kc16(4)][nf(16)][l(32)] x 16B   (32 MB)
// g_xp2: [mblk(64)][it64(64)][kc16(4)][f(8)][l(32)] x 16B     (64 MB)
__device__ __half g_wt2[(size_t)NDIM * KDIM];
__device__ __half g_xp2[(size_t)MDIM * KDIM];

// ---------------- helpers ----------------
__device__ __forceinline__ uint32_t smem_u32(const void* p) {
    uint32_t a;
    asm("{ .reg .u64 t; cvta.to.shared.u64 t, %1; cvt.u32.u64 %0, t; }" : "=r"(a) : "l"(p));
    return a;
}
__device__ __forceinline__ uint4 lds128(uint32_t a) {
    uint4 v;
    asm volatile("ld.shared.v4.b32 {%0,%1,%2,%3}, [%4];"
                 : "=r"(v.x), "=r"(v.y), "=r"(v.z), "=r"(v.w) : "r"(a));
    return v;
}
__device__ __forceinline__ void cp16(uint32_t dst, const void* src) {
    asm volatile("cp.async.cg.shared.global [%0], [%1], 16;" :: "r"(dst), "l"(src) : "memory");
}
__device__ __forceinline__ void mma16816(float* d, uint32_t a0, uint32_t a1, uint32_t a2,
                                         uint32_t a3, uint32_t b0, uint32_t b1) {
    asm volatile(
        "mma.sync.aligned.m16n8k16.row.col.f32.f16.f16.f32 "
        "{%0,%1,%2,%3}, {%4,%5,%6,%7}, {%8,%9}, {%0,%1,%2,%3};"
        : "+f"(d[0]), "+f"(d[1]), "+f"(d[2]), "+f"(d[3])
        : "r"(a0), "r"(a1), "r"(a2), "r"(a3), "r"(b0), "r"(b1));
}

// ------- kernel 1: merged prep, fragment-major outputs (unchanged) -------
__global__ void __launch_bounds__(256) prep_kernel(const int* __restrict__ qw,
                                                   const int* __restrict__ qz,
                                                   const float* __restrict__ sc,
                                                   const float* __restrict__ x) {
    if (blockIdx.x < DQ_BLOCKS) {
        int idx = blockIdx.x * 256 + threadIdx.x;   // 2M
        int l = idx & 31;
        int nf = (idx >> 5) & 15;
        int kc16 = (idx >> 9) & 3;
        int it = (idx >> 11) & 63;
        int nblk = idx >> 17;
        int b = l & 3;
        int n = nblk * 256 + nf * 16 + (l >> 2);
        int n8 = n + 8;
        int k0 = it * 64 + kc16 * 16;
        int r0 = k0 >> 3;
        int grp = k0 >> 7;
        int zp  = qz[grp * (NDIM / 8) + (n >> 3)];
        int zp8 = qz[grp * (NDIM / 8) + (n8 >> 3)];
        int z  = ((zp  >> ((n  & 7) * 4)) & 15) + 1;
        int z8 = ((zp8 >> ((n8 & 7) * 4)) & 15) + 1;
        float s  = sc[grp * NDIM + n];
        float s8 = sc[grp * NDIM + n8];
        int q00 = qw[(size_t)r0 * NDIM + n];
        int q10 = qw[(size_t)(r0 + 1) * NDIM + n];
        int q08 = qw[(size_t)r0 * NDIM + n8];
        int q18 = qw[(size_t)(r0 + 1) * NDIM + n8];
        __half2 o[4];
        o[0] = __floats2half2_rn(s  * (float)(((q00 >> (8 * b)) & 15) - z),
                                 s  * (float)(((q00 >> (8 * b + 4)) & 15) - z));
        o[1] = __floats2half2_rn(s  * (float)(((q10 >> (8 * b)) & 15) - z),
                                 s  * (float)(((q10 >> (8 * b + 4)) & 15) - z));
        o[2] = __floats2half2_rn(s8 * (float)(((q08 >> (8 * b)) & 15) - z8),
                                 s8 * (float)(((q08 >> (8 * b + 4)) & 15) - z8));
        o[3] = __floats2half2_rn(s8 * (float)(((q18 >> (8 * b)) & 15) - z8),
                                 s8 * (float)(((q18 >> (8 * b + 4)) & 15) - z8));
        ((uint4*)g_wt2)[idx] = *(uint4*)&o[0];
    } else {
        int idx = (blockIdx.x - DQ_BLOCKS) * 256 + threadIdx.x;  // 4M
        int l = idx & 31;
        int f = (idx >> 5) & 7;
        int kc16 = (idx >> 8) & 3;
        int it = (idx >> 10) & 63;
        int mblk = idx >> 16;
        int b = l & 3;
        int r = mblk * 128 + f * 16 + (l >> 2);
        int k0 = it * 64 + kc16 * 16 + 2 * b;
        const float* xr = x + (size_t)r * KDIM;
        float2 lo  = *(const float2*)(xr + k0);
        float2 hi  = *(const float2*)(xr + k0 + 8);
        float2 lo8 = *(const float2*)(xr + 8 * KDIM + k0);
        float2 hi8 = *(const float2*)(xr + 8 * KDIM + k0 + 8);
        __half2 o[4];
        o[0] = __floats2half2_rn(lo.x, lo.y);
        o[1] = __floats2half2_rn(lo8.x, lo8.y);
        o[2] = __floats2half2_rn(hi.x, hi.y);
        o[3] = __floats2half2_rn(hi8.x, hi8.y);
        ((uint4*)g_xp2)[idx] = *(uint4*)&o[0];
    }
}

// ---- kernel 2: fp16 mma.sync GEMM, BK=128, fetch smeared across MMA groups ----
__global__ void __launch_bounds__(256, 1)
gemm_kernel(const float* __restrict__ bias, float* __restrict__ out) {
    extern __shared__ char smem_raw[];
    uint32_t sbase = smem_u32(smem_raw);
    int tid = threadIdx.x;
    int l = tid & 31;
    int wid = tid >> 5;
    int wm = wid & 1;       // 2 m-warps (64 rows each)
    int wn = wid >> 1;      // 4 n-warps (64 cols each)

    // supertile: 8 m-tiles x 16 n-tiles (full N) -> W (32MB fp16) L2-resident
    int bid = blockIdx.x;
    int sup = bid >> 7;
    int loc = bid & 127;
    int mblk = sup * 8 + (loc & 7);
    int nblk = loc >> 3;
    int m0 = mblk * BM;
    int n0 = nblk * BN;

    const char* a_gbase = (const char*)g_xp2 + (size_t)mblk * 64 * 16384;
    const char* b_gbase = (const char*)g_wt2 + (size_t)nblk * 64 * 32768;

    // full fetch (prologue only)
    auto fetch_all = [&](int it) {
        int s = it & 1;
        uint32_t sa = sbase + s * STAGE_BYTES;
        const char* ga = a_gbase + (size_t)it * A_STAGE;
        const char* gb = b_gbase + (size_t)it * B_STAGE;
#pragma unroll
        for (int i = 0; i < 8; ++i)
            cp16(sa + tid * 16 + i * 4096, ga + tid * 16 + i * 4096);
#pragma unroll
        for (int i = 0; i < 16; ++i)
            cp16(sa + A_STAGE + tid * 16 + i * 4096, gb + tid * 16 + i * 4096);
    };

    fetch_all(0);
    asm volatile("cp.async.commit_group;" ::: "memory");

    uint32_t aoff = (uint32_t)(wm * 2048 + l * 16);   // + g*4096 + ms*512
    uint32_t boff = (uint32_t)(wn * 2048 + l * 16);   // + g*8192 + p*512

    float acc[4][8][4];
#pragma unroll
    for (int ms = 0; ms < 4; ++ms)
#pragma unroll
        for (int ns = 0; ns < 8; ++ns)
#pragma unroll
            for (int i = 0; i < 4; ++i) acc[ms][ns][i] = 0.f;

    for (int it = 0; it < KITERS; ++it) {
        asm volatile("cp.async.wait_group 0;" ::: "memory");
        __syncthreads();

        uint32_t sa = sbase + (it & 1) * STAGE_BYTES;
        uint32_t sb = sa + A_STAGE;
        // next-stage fetch pointers (smeared into groups 0..3 below)
        uint32_t da = sbase + ((it + 1) & 1) * STAGE_BYTES + tid * 16;
        const char* ga = a_gbase + (size_t)(it + 1) * A_STAGE + tid * 16;
        const char* gb = b_gbase + (size_t)(it + 1) * B_STAGE + tid * 16;
        bool more = (it + 1 < KITERS);

        uint4 aq[2][4], bq[2][4];
#pragma unroll
        for (int ms = 0; ms < 4; ++ms) aq[0][ms] = lds128(sa + aoff + ms * 512);
#pragma unroll
        for (int p = 0; p < 4; ++p) bq[0][p] = lds128(sb + boff + p * 512);

#pragma unroll
        for (int g = 0; g < 8; ++g) {           // 8 uniform k16 groups (BK=128)
            int cur = g & 1, nxt = cur ^ 1;
            if (g < 7) {                        // prefetch group g+1 fragments
#pragma unroll
                for (int ms = 0; ms < 4; ++ms)
                    aq[nxt][ms] = lds128(sa + (g + 1) * 4096 + aoff + ms * 512);
#pragma unroll
                for (int p = 0; p < 4; ++p)
                    bq[nxt][p] = lds128(sb + (g + 1) * 8192 + boff + p * 512);
            }
            // smear next-stage cp.async: 6 per group over groups 0..3
            if (more && g < 4) {
#pragma unroll
                for (int j = 0; j < 6; ++j) {
                    int i = g * 6 + j;          // 0..23: A first 8, then B 16
                    if (i < 8) cp16(da + i * 4096, ga + i * 4096);
                    else       cp16(da + A_STAGE + (i - 8) * 4096, gb + (i - 8) * 4096);
                }
            }
#pragma unroll
            for (int ms = 0; ms < 4; ++ms) {
#pragma unroll
                for (int p = 0; p < 4; ++p) {
                    mma16816(acc[ms][2 * p], aq[cur][ms].x, aq[cur][ms].y,
                             aq[cur][ms].z, aq[cur][ms].w, bq[cur][p].x, bq[cur][p].y);
                    mma16816(acc[ms][2 * p + 1], aq[cur][ms].x, aq[cur][ms].y,
                             aq[cur][ms].z, aq[cur][ms].w, bq[cur][p].z, bq[cur][p].w);
                }
            }
            if (g == 4) asm volatile("cp.async.commit_group;" ::: "memory");
        }
    }

    // --- epilogue: acc + bias -> out ---
#pragma unroll
    for (int ms = 0; ms < 4; ++ms) {
        int row = m0 + wm * 64 + ms * 16 + (l >> 2);
#pragma unroll
        for (int ns = 0; ns < 8; ++ns) {
            int col = n0 + wn * 64 + (ns >> 1) * 16 + (ns & 1) * 8 + 2 * (l & 3);
            float2 b2 = *(const float2*)(bias + col);
            float2 v0 = make_float2(acc[ms][ns][0] + b2.x, acc[ms][ns][1] + b2.y);
            float2 v1 = make_float2(acc[ms][ns][2] + b2.x, acc[ms][ns][3] + b2.y);
            *(float2*)(out + (size_t)row * NDIM + col) = v0;
            *(float2*)(out + (size_t)(row + 8) * NDIM + col) = v1;
        }
    }
}

// ---------------- launch ----------------
extern "C" void kernel_launch(void* const* d_in, const int* in_sizes, int n_in,
                              void* d_out, int out_size) {
    const float* x    = (const float*)d_in[0];
    const int*   qw   = (const int*)d_in[1];
    const int*   qz   = (const int*)d_in[2];
    const float* sc   = (const float*)d_in[3];
    const float* bias = (const float*)d_in[4];
    float* out = (float*)d_out;

    prep_kernel<<<DQ_BLOCKS + XP_BLOCKS, 256>>>(qw, qz, sc, x);

    cudaFuncSetAttribute(gemm_kernel, cudaFuncAttributeMaxDynamicSharedMemorySize, SMEM_TOTAL);
    gemm_kernel<<<(MDIM / BM) * (NDIM / BN), 256, SMEM_TOTAL>>>(bias, out);
}